// round 13
// baseline (speedup 1.0000x reference)
#include <cuda_runtime.h>
#include <cuda_fp16.h>
#include <math.h>
#include <stdint.h>
#include <string.h>

#define Bq   32
#define Tt   512
#define FDim 256
#define NH   1024
#define NC   512
#define G4   2048      // 4*NC
#define G8   4096      // 2 dirs * 4*NC
#define NOUT 8
#define MT   (Bq*Tt)   // 16384 rows
#define LSTM_BLOCKS 128

// ---------------- device scratch ----------------
__device__ float  g_h1[(size_t)MT*NH];
__device__ float  g_h2[(size_t)MT*NH];
__device__ float  g_xp[(size_t)MT*G8];         // [(b*T+t)][dir*G4 + g]
__device__ float  g_l1[(size_t)MT*2*NC];
__device__ __half g_hbufh[4][Bq*NC];           // [dir*2+parity][b][j], fp16 h state
__device__ float  g_sc[Bq*Tt];
__device__ float  g_pooled[Bq*2*NC];
__device__ __half g_xh[(size_t)MT*FDim];
__device__ __half g_h1h[(size_t)MT*NH];
__device__ __half g_h2h[(size_t)MT*NH];
__device__ __half g_l0h[(size_t)MT*2*NC];
__device__ __half g_w1h[(size_t)NH*FDim];
__device__ __half g_w2h[(size_t)NH*NH];
__device__ __half g_wihh[(size_t)2*G8*NH];
__device__ unsigned g_flags[LSTM_BLOCKS];

// ---------------- grid barrier: per-block flag array ----------------
// stores ordered by __syncthreads (block scope) + thread-0 fence.gpu (CG pattern)
__device__ __forceinline__ void gridbar(unsigned &gen) {
    gen++;
    __syncthreads();
    const int tid = threadIdx.x;
    if (tid == 0) {
        asm volatile("fence.acq_rel.gpu;" ::: "memory");
        asm volatile("st.relaxed.gpu.u32 [%0], %1;"
                     :: "l"(&g_flags[blockIdx.x]), "r"(gen) : "memory");
    }
    if (tid < LSTM_BLOCKS) {
        unsigned cur;
        do {
            asm volatile("ld.acquire.gpu.u32 %0, [%1];"
                         : "=r"(cur) : "l"(&g_flags[tid]) : "memory");
        } while (cur < gen);
    }
    __syncthreads();
}

__global__ void reset_bar_kernel() {
    if (threadIdx.x < LSTM_BLOCKS) g_flags[threadIdx.x] = 0u;
}

// ---------------- helpers ----------------
__device__ __forceinline__ unsigned su32(const void* p) {
    unsigned r;
    asm("{.reg .u64 t; cvta.to.shared.u64 t, %1; cvt.u32.u64 %0, t;}" : "=r"(r) : "l"(p));
    return r;
}
__device__ __forceinline__ void cp16(unsigned s, const void* g) {
    asm volatile("cp.async.cg.shared.global [%0], [%1], 16;\n" :: "r"(s), "l"(g));
}
__device__ __forceinline__ uint32_t h2_as_u32(__half2 h) {
    __half2_raw r = *(__half2_raw*)&h;
    return (uint32_t)r.x | ((uint32_t)r.y << 16);
}
__device__ __forceinline__ float fexp(float x) {
    float r;
    asm("ex2.approx.f32 %0, %1;" : "=f"(r) : "f"(x * 1.4426950408889634f));
    return r;
}
__device__ __forceinline__ float fsig(float x) {
    return __fdividef(1.f, 1.f + fexp(-x));
}
__device__ __forceinline__ float ftanh(float x) {
    const float xx = fminf(fmaxf(x, -15.f), 15.f);
    const float e = fexp(2.f * xx);
    return __fdividef(e - 1.f, e + 1.f);
}
__device__ __forceinline__ void mma_f16(float (&c)[4], const uint32_t (&a)[4], const uint32_t (&b)[2]) {
    asm volatile("mma.sync.aligned.m16n8k16.row.col.f32.f16.f16.f32 "
        "{%0,%1,%2,%3}, {%4,%5,%6,%7}, {%8,%9}, {%0,%1,%2,%3};\n"
        : "+f"(c[0]), "+f"(c[1]), "+f"(c[2]), "+f"(c[3])
        : "r"(a[0]), "r"(a[1]), "r"(a[2]), "r"(a[3]), "r"(b[0]), "r"(b[1]));
}

// ---------------- elementwise fp32 -> fp16 ----------------
__global__ __launch_bounds__(256) void cvt_f16_kernel(
    const float4* __restrict__ src, uint2* __restrict__ dst, int n4)
{
    const int i = blockIdx.x * 256 + threadIdx.x;
    if (i < n4) {
        float4 v = src[i];
        uint2 o;
        o.x = h2_as_u32(__floats2half2_rn(v.x, v.y));
        o.y = h2_as_u32(__floats2half2_rn(v.z, v.w));
        dst[i] = o;
    }
}

// ---------------- fp16 GEMM: C = A[M,K]*W[N,K]^T + b1 (+b2), fp32 accum/out ----------------
#define PADH 40
__global__ __launch_bounds__(256) void gemm_f16_kernel(
    const __half* __restrict__ A, const __half* __restrict__ W,
    const float* __restrict__ bias1, const float* __restrict__ bias2,
    float* __restrict__ C, int M, int N, int K)
{
    __shared__ __half As[2][128 * PADH];
    __shared__ __half Ws[2][128 * PADH];
    const int tid  = threadIdx.x;
    const int warp = tid >> 5, lane = tid & 31;
    const int wm = warp & 3, wn = warp >> 2;
    const int qr = lane >> 2, qk = lane & 3;
    const int m0 = blockIdx.y * 128;
    const int n0 = blockIdx.x * 128;

    const int ca = tid * 2, cb = ca + 1;
    const int ra = ca >> 2, ka = (ca & 3) * 8;
    const int rb = cb >> 2, kb = (cb & 3) * 8;

    const __half* Ag = A + (size_t)m0 * K;
    const __half* Wg = W + (size_t)n0 * K;

    const unsigned sAa = su32(&As[0][ra * PADH + ka]);
    const unsigned sAb = su32(&As[0][rb * PADH + kb]);
    const unsigned sWa = su32(&Ws[0][ra * PADH + ka]);
    const unsigned sWb = su32(&Ws[0][rb * PADH + kb]);
    const unsigned stgB = 128 * PADH * 2;

    float acc[2][8][4];
#pragma unroll
    for (int i = 0; i < 2; i++)
#pragma unroll
        for (int j = 0; j < 8; j++)
#pragma unroll
            for (int l = 0; l < 4; l++) acc[i][j][l] = 0.f;

    const int nk = K >> 5;

    cp16(sAa, Ag + (size_t)ra * K + ka);
    cp16(sAb, Ag + (size_t)rb * K + kb);
    cp16(sWa, Wg + (size_t)ra * K + ka);
    cp16(sWb, Wg + (size_t)rb * K + kb);
    asm volatile("cp.async.commit_group;\n");

    for (int kt = 0; kt < nk; kt++) {
        if (kt + 1 < nk) {
            const int k0 = (kt + 1) * 32;
            const unsigned so = ((kt + 1) & 1) * stgB;
            cp16(sAa + so, Ag + (size_t)ra * K + k0 + ka);
            cp16(sAb + so, Ag + (size_t)rb * K + k0 + kb);
            cp16(sWa + so, Wg + (size_t)ra * K + k0 + ka);
            cp16(sWb + so, Wg + (size_t)rb * K + k0 + kb);
            asm volatile("cp.async.commit_group;\n");
            asm volatile("cp.async.wait_group 1;\n");
        } else {
            asm volatile("cp.async.wait_group 0;\n");
        }
        __syncthreads();

        const uint32_t* Ab_ = (const uint32_t*)&As[kt & 1][0];
        const uint32_t* Bb_ = (const uint32_t*)&Ws[kt & 1][0];
#pragma unroll
        for (int ks = 0; ks < 32; ks += 16) {
            uint32_t a[2][4];
#pragma unroll
            for (int mt = 0; mt < 2; mt++) {
                const uint32_t* ap = Ab_ + (wm * 32 + mt * 16 + qr) * (PADH / 2) + (ks >> 1) + qk;
                a[mt][0] = ap[0];
                a[mt][1] = ap[8 * (PADH / 2)];
                a[mt][2] = ap[4];
                a[mt][3] = ap[8 * (PADH / 2) + 4];
            }
#pragma unroll
            for (int nt = 0; nt < 8; nt++) {
                const uint32_t* bp = Bb_ + (wn * 64 + nt * 8 + qr) * (PADH / 2) + (ks >> 1) + qk;
                uint32_t b[2];
                b[0] = bp[0];
                b[1] = bp[4];
                mma_f16(acc[0][nt], a[0], b);
                mma_f16(acc[1][nt], a[1], b);
            }
        }
        __syncthreads();
    }

#pragma unroll
    for (int mt = 0; mt < 2; mt++) {
        const int mr = m0 + wm * 32 + mt * 16 + qr;
#pragma unroll
        for (int nt = 0; nt < 8; nt++) {
            const int n = n0 + wn * 64 + nt * 8 + qk * 2;
            float b0 = bias1[n], b1 = bias1[n + 1];
            if (bias2) { b0 += bias2[n]; b1 += bias2[n + 1]; }
            *(float2*)&C[(size_t)mr * N + n]       = make_float2(acc[mt][nt][0] + b0, acc[mt][nt][1] + b1);
            *(float2*)&C[(size_t)(mr + 8) * N + n] = make_float2(acc[mt][nt][2] + b0, acc[mt][nt][3] + b1);
        }
    }
}

// ---------------- LayerNorm + LeakyReLU (+ mask): fp32 in, fp16 out ----------------
__global__ __launch_bounds__(256) void ln_lrelu_kernel(
    const float* __restrict__ X, __half* __restrict__ Xh,
    const float* __restrict__ gm, const float* __restrict__ bt,
    const int* __restrict__ lens, int domask)
{
    const int row = blockIdx.x;
    const int tid = threadIdx.x;
    const float4* Xr = (const float4*)(X + (size_t)row * NH);
    float4 v = Xr[tid];
    __shared__ float rs[256], rq[256];
    rs[tid] = v.x + v.y + v.z + v.w;
    rq[tid] = v.x * v.x + v.y * v.y + v.z * v.z + v.w * v.w;
    __syncthreads();
    for (int o = 128; o; o >>= 1) {
        if (tid < o) { rs[tid] += rs[tid + o]; rq[tid] += rq[tid + o]; }
        __syncthreads();
    }
    const float mean = rs[0] * (1.f / NH);
    const float var  = rq[0] * (1.f / NH) - mean * mean;
    const float rstd = rsqrtf(var + 1e-5f);
    float mul = 1.f;
    if (domask) {
        const int b = row >> 9, t = row & 511;
        if (t >= lens[b]) mul = 0.f;
    }
    const int gb = tid * 4;
    float y0 = (v.x - mean) * rstd * gm[gb + 0] + bt[gb + 0];
    float y1 = (v.y - mean) * rstd * gm[gb + 1] + bt[gb + 1];
    float y2 = (v.z - mean) * rstd * gm[gb + 2] + bt[gb + 2];
    float y3 = (v.w - mean) * rstd * gm[gb + 3] + bt[gb + 3];
    y0 = (y0 >= 0.f ? y0 : 0.01f * y0) * mul;
    y1 = (y1 >= 0.f ? y1 : 0.01f * y1) * mul;
    y2 = (y2 >= 0.f ? y2 : 0.01f * y2) * mul;
    y3 = (y3 >= 0.f ? y3 : 0.01f * y3) * mul;
    uint2 o;
    o.x = h2_as_u32(__floats2half2_rn(y0, y1));
    o.y = h2_as_u32(__floats2half2_rn(y2, y3));
    ((uint2*)(Xh + (size_t)row * NH))[tid] = o;
}

// ---------------- persistent fp16 tensor-core bidirectional LSTM layer ----------------
// 128 blocks x 256 threads. d = bid>>6; block owns 8 hidden units (32 N-cols).
// Warps: kh = warp>>2 (K half), wn = warp&3 (ncols 8wn..8wn+7).
// Activation: 1 (b,j) pair per thread.
#define HPADH 520
#define GPADL 36
__global__ __launch_bounds__(256, 1) void lstm_tc_kernel(
    const float* __restrict__ xp,    // [MT][G8], dir at col offset d*G4
    const float* __restrict__ whh,   // [2][G4][NC] for this layer
    float* __restrict__ out,         // optional fp32 out [(b*T+t)][2*NC]
    __half* __restrict__ outh)       // optional fp16 out
{
    extern __shared__ char smraw[];
    __half* Hs = (__half*)smraw;                    // 32 x HPADH halves
    float*  Gs = (float*)(smraw + 32 * HPADH * 2);  // 2 x 32 x GPADL floats

    const int tid  = threadIdx.x;
    const int warp = tid >> 5, lane = tid & 31;
    const int qr = lane >> 2, qk = lane & 3;
    const int d   = blockIdx.x >> 6;
    const int j0  = (blockIdx.x & 63) * 8;
    const int kh  = warp >> 2, wn = warp & 3;

    // B fragments (fp16): ncol = 8*wn + qr; K-half kh
    const int ncol = 8 * wn + qr;
    const int jl_w = ncol >> 2, ty_w = ncol & 3;
    const int grow = ty_w * NC + j0 + jl_w;
    const float* wrow = whh + (size_t)d * G4 * NC + (size_t)grow * NC + kh * 256;
    uint32_t b0r[16], b1r[16];
#pragma unroll
    for (int kt = 0; kt < 16; kt++) {
        const float w0 = __ldg(wrow + kt * 16 + 2 * qk);
        const float w1 = __ldg(wrow + kt * 16 + 2 * qk + 1);
        const float w2 = __ldg(wrow + kt * 16 + 2 * qk + 8);
        const float w3 = __ldg(wrow + kt * 16 + 2 * qk + 9);
        b0r[kt] = h2_as_u32(__floats2half2_rn(w0, w1));
        b1r[kt] = h2_as_u32(__floats2half2_rn(w2, w3));
    }

    // activation mapping: one (b, j) per thread
    const int ab = tid >> 3, ajl = tid & 7, aj = j0 + ajl;
    const float* xpd = xp + (size_t)d * G4;
    float cst = 0.f;
    unsigned gen = 0;

    // prefetch xp for t = 0
    int tt0 = d ? (Tt - 1) : 0;
    const float* xpr0 = xpd + ((size_t)ab * Tt + tt0) * G8;
    float pxi = __ldg(xpr0 + aj);
    float pxf = __ldg(xpr0 + NC + aj);
    float pxg = __ldg(xpr0 + 2 * NC + aj);
    float pxo = __ldg(xpr0 + 3 * NC + aj);

    for (int t = 0; t < Tt; t++) {
        const int tt = d ? (Tt - 1 - t) : t;

        if (t > 0) {
            // stage fp16 h_{t-1}: 32 rows x 512 halves = 2048 uint4
            const uint4* src = (const uint4*)g_hbufh[d * 2 + (t & 1)];
#pragma unroll
            for (int r = 0; r < 8; r++) {
                const int idx = r * 256 + tid;
                uint4 v = __ldcg(src + idx);
                const int row = idx >> 6, col = idx & 63;
                *(uint4*)(Hs + row * HPADH + col * 8) = v;
            }
            __syncthreads();

            float acc[2][4];
#pragma unroll
            for (int mt = 0; mt < 2; mt++)
#pragma unroll
                for (int l = 0; l < 4; l++) acc[mt][l] = 0.f;

            const uint32_t* Hs32 = (const uint32_t*)Hs;
            const int kb_ = kh * 16;
#pragma unroll
            for (int kt = 0; kt < 16; kt++) {
                uint32_t b[2] = { b0r[kt], b1r[kt] };
#pragma unroll
                for (int mt = 0; mt < 2; mt++) {
                    const uint32_t* ap = Hs32 + (16 * mt + qr) * (HPADH / 2) + (kb_ + kt) * 8 + qk;
                    uint32_t a[4];
                    a[0] = ap[0];
                    a[1] = ap[8 * (HPADH / 2)];
                    a[2] = ap[4];
                    a[3] = ap[8 * (HPADH / 2) + 4];
                    mma_f16(acc[mt], a, b);
                }
            }
            float* Gk = Gs + kh * 32 * GPADL;
#pragma unroll
            for (int mt = 0; mt < 2; mt++) {
                *(float2*)&Gk[(16 * mt + qr) * GPADL + 8 * wn + 2 * qk] =
                    make_float2(acc[mt][0], acc[mt][1]);
                *(float2*)&Gk[(16 * mt + qr + 8) * GPADL + 8 * wn + 2 * qk] =
                    make_float2(acc[mt][2], acc[mt][3]);
            }
            __syncthreads();
        }

        // ---- activation: single (b, j) per thread ----
        {
            float gi = pxi, gf = pxf, gg = pxg, go = pxo;
            if (t > 0) {
                float4 g0 = *(const float4*)&Gs[ab * GPADL + 4 * ajl];
                float4 g1 = *(const float4*)&Gs[32 * GPADL + ab * GPADL + 4 * ajl];
                gi += g0.x + g1.x; gf += g0.y + g1.y;
                gg += g0.z + g1.z; go += g0.w + g1.w;
            }
            const float si = fsig(gi);
            const float sf = fsig(gf);
            const float sg = ftanh(gg);
            const float so = fsig(go);
            cst = sf * cst + si * sg;
            const float h = so * ftanh(cst);
            __stcg((__half*)&g_hbufh[d * 2 + ((t + 1) & 1)][ab * NC + aj], __float2half_rn(h));
            const size_t oidx = ((size_t)ab * Tt + tt) * (2 * NC) + d * NC + aj;
            if (out)  out[oidx]  = h;
            if (outh) outh[oidx] = __float2half_rn(h);
        }

        // prefetch xp for t+1 (independent of h) before the barrier
        if (t + 1 < Tt) {
            const int ttn = d ? (Tt - 2 - t) : (t + 1);
            const float* xpr = xpd + ((size_t)ab * Tt + ttn) * G8;
            pxi = __ldg(xpr + aj);
            pxf = __ldg(xpr + NC + aj);
            pxg = __ldg(xpr + 2 * NC + aj);
            pxo = __ldg(xpr + 3 * NC + aj);
            gridbar(gen);
        }
    }
}

// ---------------- attention scores ----------------
__global__ __launch_bounds__(256) void scores_kernel(
    const float* __restrict__ h, const float* __restrict__ wu,
    const float* __restrict__ bu, const int* __restrict__ lens,
    float* __restrict__ sc)
{
    const int gid = blockIdx.x * 256 + threadIdx.x;
    const int w = gid >> 5, lane = gid & 31;
    const float* hr = h + (size_t)w * (2 * NC);
    float s = 0.f;
    for (int i = lane; i < 2 * NC; i += 32) s = fmaf(hr[i], wu[i], s);
#pragma unroll
    for (int o = 16; o; o >>= 1) s += __shfl_xor_sync(0xffffffffu, s, o);
    if (lane == 0) {
        const int b = w >> 9, t = w & 511;
        sc[w] = (t < lens[b]) ? (s + bu[0]) : -INFINITY;
    }
}

// ---------------- masked softmax + weighted pool ----------------
__global__ __launch_bounds__(256) void softpool_kernel(
    const float* __restrict__ h, const float* __restrict__ sc,
    float* __restrict__ pooled)
{
    const int b = blockIdx.x, tid = threadIdx.x;
    __shared__ float al[512];
    __shared__ float red[256];
    float m = -INFINITY;
    for (int t = tid; t < 512; t += 256) m = fmaxf(m, sc[b * 512 + t]);
    red[tid] = m; __syncthreads();
    for (int o = 128; o; o >>= 1) {
        if (tid < o) red[tid] = fmaxf(red[tid], red[tid + o]);
        __syncthreads();
    }
    m = red[0]; __syncthreads();
    float s = 0.f;
    for (int t = tid; t < 512; t += 256) {
        const float e = expf(sc[b * 512 + t] - m);
        al[t] = e; s += e;
    }
    red[tid] = s; __syncthreads();
    for (int o = 128; o; o >>= 1) {
        if (tid < o) red[tid] += red[tid + o];
        __syncthreads();
    }
    const float inv = 1.f / red[0];
    __syncthreads();
    for (int d2 = tid; d2 < 2 * NC; d2 += 256) {
        float acc = 0.f;
        for (int t = 0; t < 512; t++)
            acc = fmaf(al[t], h[((size_t)b * 512 + t) * (2 * NC) + d2], acc);
        pooled[b * (2 * NC) + d2] = acc * inv;
    }
}

// ---------------- final classifier ----------------
__global__ __launch_bounds__(256) void final_kernel(
    const float* __restrict__ pooled, const float* __restrict__ Wc,
    const float* __restrict__ bc, float* __restrict__ out)
{
    const int tid = threadIdx.x;
    const int b = tid >> 3, o = tid & 7;
    const float* p = pooled + b * (2 * NC);
    const float* w = Wc + o * (2 * NC);
    float acc = bc[o];
    for (int k = 0; k < 2 * NC; k++) acc = fmaf(p[k], w[k], acc);
    out[b * NOUT + o] = acc;
}

// ---------------- launch ----------------
extern "C" void kernel_launch(void* const* d_in, const int* in_sizes, int n_in,
                              void* d_out, int out_size)
{
    const float* x    = (const float*)d_in[0];
    const int*   lens = (const int*)  d_in[1];
    const float* W1   = (const float*)d_in[2];
    const float* b1   = (const float*)d_in[3];
    const float* g1   = (const float*)d_in[4];
    const float* be1  = (const float*)d_in[5];
    const float* W2   = (const float*)d_in[6];
    const float* b2   = (const float*)d_in[7];
    const float* g2   = (const float*)d_in[8];
    const float* be2  = (const float*)d_in[9];
    const float* wih  = (const float*)d_in[10];
    const float* whh  = (const float*)d_in[11];
    const float* bih  = (const float*)d_in[12];
    const float* bhh  = (const float*)d_in[13];
    const float* wu   = (const float*)d_in[14];
    const float* bu   = (const float*)d_in[15];
    const float* Wc   = (const float*)d_in[16];
    const float* bc   = (const float*)d_in[17];
    float* out = (float*)d_out;

    float  *h1, *h2, *xpb, *l1, *sc, *pooled;
    __half *xh, *h1h, *h2h, *l0h, *w1h, *w2h, *wihh;
    cudaGetSymbolAddress((void**)&h1, g_h1);
    cudaGetSymbolAddress((void**)&h2, g_h2);
    cudaGetSymbolAddress((void**)&xpb, g_xp);
    cudaGetSymbolAddress((void**)&l1, g_l1);
    cudaGetSymbolAddress((void**)&sc, g_sc);
    cudaGetSymbolAddress((void**)&pooled, g_pooled);
    cudaGetSymbolAddress((void**)&xh, g_xh);
    cudaGetSymbolAddress((void**)&h1h, g_h1h);
    cudaGetSymbolAddress((void**)&h2h, g_h2h);
    cudaGetSymbolAddress((void**)&l0h, g_l0h);
    cudaGetSymbolAddress((void**)&w1h, g_w1h);
    cudaGetSymbolAddress((void**)&w2h, g_w2h);
    cudaGetSymbolAddress((void**)&wihh, g_wihh);

    const int lstm_smem = 32 * HPADH * 2 + 2 * 32 * GPADL * 4;
    cudaFuncSetAttribute(lstm_tc_kernel,
                         cudaFuncAttributeMaxDynamicSharedMemorySize, lstm_smem);

    // one-shot fp32 -> fp16 operand conversion
    cvt_f16_kernel<<<(MT * FDim / 4 + 255) / 256, 256>>>((const float4*)x, (uint2*)xh, MT * FDim / 4);
    cvt_f16_kernel<<<(NH * FDim / 4 + 255) / 256, 256>>>((const float4*)W1, (uint2*)w1h, NH * FDim / 4);
    cvt_f16_kernel<<<(NH * NH / 4 + 255) / 256, 256>>>((const float4*)W2, (uint2*)w2h, NH * NH / 4);
    cvt_f16_kernel<<<(2 * G8 * NH / 4 + 255) / 256, 256>>>((const float4*)wih, (uint2*)wihh, 2 * G8 * NH / 4);

    // MLP
    gemm_f16_kernel<<<dim3(NH / 128, MT / 128), 256>>>(xh, w1h, b1, nullptr, h1, MT, NH, FDim);
    ln_lrelu_kernel<<<MT, 256>>>(h1, h1h, g1, be1, nullptr, 0);
    gemm_f16_kernel<<<dim3(NH / 128, MT / 128), 256>>>(h1h, w2h, b2, nullptr, h2, MT, NH, NH);
    ln_lrelu_kernel<<<MT, 256>>>(h2, h2h, g2, be2, lens, 1);

    // LSTM layer 0: fp16 out only (feeds layer-1 GEMM)
    gemm_f16_kernel<<<dim3(G8 / 128, MT / 128), 256>>>(
        h2h, wihh, bih, bhh, xpb, MT, G8, NH);
    reset_bar_kernel<<<1, 128>>>();
    lstm_tc_kernel<<<LSTM_BLOCKS, 256, lstm_smem>>>(xpb, whh, nullptr, l0h);

    // LSTM layer 1: fp32 out only (feeds attention)
    gemm_f16_kernel<<<dim3(G8 / 128, MT / 128), 256>>>(
        l0h, wihh + (size_t)G8 * NH,
        bih + G8, bhh + G8, xpb, MT, G8, NH);
    reset_bar_kernel<<<1, 128>>>();
    lstm_tc_kernel<<<LSTM_BLOCKS, 256, lstm_smem>>>(xpb, whh + (size_t)2 * G4 * NC, l1, nullptr);

    // attention + head
    scores_kernel<<<MT / 8, 256>>>(l1, wu, bu, lens, sc);
    softpool_kernel<<<Bq, 256>>>(l1, sc, pooled);
    final_kernel<<<1, 256>>>(pooled, Wc, bc, out);
}

// round 14
// speedup vs baseline: 1.4797x; 1.4797x over previous
#include <cuda_runtime.h>
#include <cuda_fp16.h>
#include <math.h>
#include <stdint.h>
#include <string.h>

#define Bq   32
#define Tt   512
#define FDim 256
#define NH   1024
#define NC   512
#define G4   2048      // 4*NC
#define G8   4096      // 2 dirs * 4*NC
#define NOUT 8
#define MT   (Bq*Tt)   // 16384 rows

// ---------------- device scratch ----------------
__device__ float  g_h1[(size_t)MT*NH];
__device__ float  g_h2[(size_t)MT*NH];
__device__ float  g_xp[(size_t)MT*G8];         // [(b*T+t)][dir*G4 + g]
__device__ float  g_l1[(size_t)MT*2*NC];
__device__ __half g_hbufh[4][Bq*NC];           // [dir*2+parity][b][j], fp16 h state
__device__ float  g_sc[Bq*Tt];
__device__ float  g_pooled[Bq*2*NC];
__device__ __half g_xh[(size_t)MT*FDim];
__device__ __half g_h1h[(size_t)MT*NH];
__device__ __half g_h2h[(size_t)MT*NH];
__device__ __half g_l0h[(size_t)MT*2*NC];
__device__ __half g_w1h[(size_t)NH*FDim];
__device__ __half g_w2h[(size_t)NH*NH];
__device__ __half g_wihh[(size_t)2*G8*NH];
// per-direction barrier state, separate cache lines
__device__ unsigned g_bar_arrive2[2][32];
__device__ unsigned g_bar_gen2[2][32];

// ---------------- per-direction grid barrier (32 arrivals) ----------------
__device__ __forceinline__ void gridbar_dir(int d, unsigned nb, unsigned &gen) {
    __syncthreads();
    if (threadIdx.x == 0) {
        gen++;
        unsigned prev;
        asm volatile("atom.add.release.gpu.u32 %0, [%1], 1;"
                     : "=r"(prev) : "l"(&g_bar_arrive2[d][0]) : "memory");
        if (prev == nb * gen - 1u) {
            asm volatile("st.release.gpu.u32 [%0], %1;"
                         :: "l"(&g_bar_gen2[d][0]), "r"(gen) : "memory");
        } else {
            unsigned cur;
            do {
                asm volatile("ld.acquire.gpu.u32 %0, [%1];"
                             : "=r"(cur) : "l"(&g_bar_gen2[d][0]) : "memory");
            } while (cur < gen);
        }
    }
    __syncthreads();
}

__global__ void reset_bar_kernel() {
    if (threadIdx.x < 2) {
        g_bar_arrive2[threadIdx.x][0] = 0u;
        g_bar_gen2[threadIdx.x][0] = 0u;
    }
}

// ---------------- helpers ----------------
__device__ __forceinline__ unsigned su32(const void* p) {
    unsigned r;
    asm("{.reg .u64 t; cvta.to.shared.u64 t, %1; cvt.u32.u64 %0, t;}" : "=r"(r) : "l"(p));
    return r;
}
__device__ __forceinline__ void cp16(unsigned s, const void* g) {
    asm volatile("cp.async.cg.shared.global [%0], [%1], 16;\n" :: "r"(s), "l"(g));
}
__device__ __forceinline__ uint32_t h2_as_u32(__half2 h) {
    __half2_raw r = *(__half2_raw*)&h;
    return (uint32_t)r.x | ((uint32_t)r.y << 16);
}
__device__ __forceinline__ float fexp(float x) {
    float r;
    asm("ex2.approx.f32 %0, %1;" : "=f"(r) : "f"(x * 1.4426950408889634f));
    return r;
}
__device__ __forceinline__ float fsig(float x) {
    return __fdividef(1.f, 1.f + fexp(-x));
}
__device__ __forceinline__ float ftanh(float x) {
    const float xx = fminf(fmaxf(x, -15.f), 15.f);
    const float e = fexp(2.f * xx);
    return __fdividef(e - 1.f, e + 1.f);
}
__device__ __forceinline__ void mma_f16(float (&c)[4], const uint32_t (&a)[4], const uint32_t (&b)[2]) {
    asm volatile("mma.sync.aligned.m16n8k16.row.col.f32.f16.f16.f32 "
        "{%0,%1,%2,%3}, {%4,%5,%6,%7}, {%8,%9}, {%0,%1,%2,%3};\n"
        : "+f"(c[0]), "+f"(c[1]), "+f"(c[2]), "+f"(c[3])
        : "r"(a[0]), "r"(a[1]), "r"(a[2]), "r"(a[3]), "r"(b[0]), "r"(b[1]));
}

// ---------------- elementwise fp32 -> fp16 ----------------
__global__ __launch_bounds__(256) void cvt_f16_kernel(
    const float4* __restrict__ src, uint2* __restrict__ dst, int n4)
{
    const int i = blockIdx.x * 256 + threadIdx.x;
    if (i < n4) {
        float4 v = src[i];
        uint2 o;
        o.x = h2_as_u32(__floats2half2_rn(v.x, v.y));
        o.y = h2_as_u32(__floats2half2_rn(v.z, v.w));
        dst[i] = o;
    }
}

// ---------------- fp16 GEMM: C = A[M,K]*W[N,K]^T + b1 (+b2), fp32 accum/out ----------------
#define PADH 40
__global__ __launch_bounds__(256) void gemm_f16_kernel(
    const __half* __restrict__ A, const __half* __restrict__ W,
    const float* __restrict__ bias1, const float* __restrict__ bias2,
    float* __restrict__ C, int M, int N, int K)
{
    __shared__ __half As[2][128 * PADH];
    __shared__ __half Ws[2][128 * PADH];
    const int tid  = threadIdx.x;
    const int warp = tid >> 5, lane = tid & 31;
    const int wm = warp & 3, wn = warp >> 2;
    const int qr = lane >> 2, qk = lane & 3;
    const int m0 = blockIdx.y * 128;
    const int n0 = blockIdx.x * 128;

    const int ca = tid * 2, cb = ca + 1;
    const int ra = ca >> 2, ka = (ca & 3) * 8;
    const int rb = cb >> 2, kb = (cb & 3) * 8;

    const __half* Ag = A + (size_t)m0 * K;
    const __half* Wg = W + (size_t)n0 * K;

    const unsigned sAa = su32(&As[0][ra * PADH + ka]);
    const unsigned sAb = su32(&As[0][rb * PADH + kb]);
    const unsigned sWa = su32(&Ws[0][ra * PADH + ka]);
    const unsigned sWb = su32(&Ws[0][rb * PADH + kb]);
    const unsigned stgB = 128 * PADH * 2;

    float acc[2][8][4];
#pragma unroll
    for (int i = 0; i < 2; i++)
#pragma unroll
        for (int j = 0; j < 8; j++)
#pragma unroll
            for (int l = 0; l < 4; l++) acc[i][j][l] = 0.f;

    const int nk = K >> 5;

    cp16(sAa, Ag + (size_t)ra * K + ka);
    cp16(sAb, Ag + (size_t)rb * K + kb);
    cp16(sWa, Wg + (size_t)ra * K + ka);
    cp16(sWb, Wg + (size_t)rb * K + kb);
    asm volatile("cp.async.commit_group;\n");

    for (int kt = 0; kt < nk; kt++) {
        if (kt + 1 < nk) {
            const int k0 = (kt + 1) * 32;
            const unsigned so = ((kt + 1) & 1) * stgB;
            cp16(sAa + so, Ag + (size_t)ra * K + k0 + ka);
            cp16(sAb + so, Ag + (size_t)rb * K + k0 + kb);
            cp16(sWa + so, Wg + (size_t)ra * K + k0 + ka);
            cp16(sWb + so, Wg + (size_t)rb * K + k0 + kb);
            asm volatile("cp.async.commit_group;\n");
            asm volatile("cp.async.wait_group 1;\n");
        } else {
            asm volatile("cp.async.wait_group 0;\n");
        }
        __syncthreads();

        const uint32_t* Ab_ = (const uint32_t*)&As[kt & 1][0];
        const uint32_t* Bb_ = (const uint32_t*)&Ws[kt & 1][0];
#pragma unroll
        for (int ks = 0; ks < 32; ks += 16) {
            uint32_t a[2][4];
#pragma unroll
            for (int mt = 0; mt < 2; mt++) {
                const uint32_t* ap = Ab_ + (wm * 32 + mt * 16 + qr) * (PADH / 2) + (ks >> 1) + qk;
                a[mt][0] = ap[0];
                a[mt][1] = ap[8 * (PADH / 2)];
                a[mt][2] = ap[4];
                a[mt][3] = ap[8 * (PADH / 2) + 4];
            }
#pragma unroll
            for (int nt = 0; nt < 8; nt++) {
                const uint32_t* bp = Bb_ + (wn * 64 + nt * 8 + qr) * (PADH / 2) + (ks >> 1) + qk;
                uint32_t b[2];
                b[0] = bp[0];
                b[1] = bp[4];
                mma_f16(acc[0][nt], a[0], b);
                mma_f16(acc[1][nt], a[1], b);
            }
        }
        __syncthreads();
    }

#pragma unroll
    for (int mt = 0; mt < 2; mt++) {
        const int mr = m0 + wm * 32 + mt * 16 + qr;
#pragma unroll
        for (int nt = 0; nt < 8; nt++) {
            const int n = n0 + wn * 64 + nt * 8 + qk * 2;
            float b0 = bias1[n], b1 = bias1[n + 1];
            if (bias2) { b0 += bias2[n]; b1 += bias2[n + 1]; }
            *(float2*)&C[(size_t)mr * N + n]       = make_float2(acc[mt][nt][0] + b0, acc[mt][nt][1] + b1);
            *(float2*)&C[(size_t)(mr + 8) * N + n] = make_float2(acc[mt][nt][2] + b0, acc[mt][nt][3] + b1);
        }
    }
}

// ---------------- LayerNorm + LeakyReLU (+ mask): fp32 in, fp16 out ----------------
__global__ __launch_bounds__(256) void ln_lrelu_kernel(
    const float* __restrict__ X, __half* __restrict__ Xh,
    const float* __restrict__ gm, const float* __restrict__ bt,
    const int* __restrict__ lens, int domask)
{
    const int row = blockIdx.x;
    const int tid = threadIdx.x;
    const float4* Xr = (const float4*)(X + (size_t)row * NH);
    float4 v = Xr[tid];
    __shared__ float rs[256], rq[256];
    rs[tid] = v.x + v.y + v.z + v.w;
    rq[tid] = v.x * v.x + v.y * v.y + v.z * v.z + v.w * v.w;
    __syncthreads();
    for (int o = 128; o; o >>= 1) {
        if (tid < o) { rs[tid] += rs[tid + o]; rq[tid] += rq[tid + o]; }
        __syncthreads();
    }
    const float mean = rs[0] * (1.f / NH);
    const float var  = rq[0] * (1.f / NH) - mean * mean;
    const float rstd = rsqrtf(var + 1e-5f);
    float mul = 1.f;
    if (domask) {
        const int b = row >> 9, t = row & 511;
        if (t >= lens[b]) mul = 0.f;
    }
    const int gb = tid * 4;
    float y0 = (v.x - mean) * rstd * gm[gb + 0] + bt[gb + 0];
    float y1 = (v.y - mean) * rstd * gm[gb + 1] + bt[gb + 1];
    float y2 = (v.z - mean) * rstd * gm[gb + 2] + bt[gb + 2];
    float y3 = (v.w - mean) * rstd * gm[gb + 3] + bt[gb + 3];
    y0 = (y0 >= 0.f ? y0 : 0.01f * y0) * mul;
    y1 = (y1 >= 0.f ? y1 : 0.01f * y1) * mul;
    y2 = (y2 >= 0.f ? y2 : 0.01f * y2) * mul;
    y3 = (y3 >= 0.f ? y3 : 0.01f * y3) * mul;
    uint2 o;
    o.x = h2_as_u32(__floats2half2_rn(y0, y1));
    o.y = h2_as_u32(__floats2half2_rn(y2, y3));
    ((uint2*)(Xh + (size_t)row * NH))[tid] = o;
}

// ---------------- persistent fp16 tensor-core bidirectional LSTM layer ----------------
// 64 blocks: d = blk>>5, block owns 16 hidden units (x4 gates = 64 N-cols).
// whh fp16 fragments in 64 registers; h state fp16 in smem; per-dir barrier;
// xp gates prefetched into registers before the barrier.
#define HPADH 520
#define GPAD  68
__global__ __launch_bounds__(256, 1) void lstm_tc_kernel(
    const float* __restrict__ xp,    // [MT][G8], dir at col offset d*G4
    const float* __restrict__ whh,   // [2][G4][NC] for this layer
    float* __restrict__ out,         // optional fp32 out [(b*T+t)][2*NC]
    __half* __restrict__ outh)       // optional fp16 out
{
    extern __shared__ char smraw[];
    __half* Hs = (__half*)smraw;                   // 32 x HPADH halves
    float*  Gs = (float*)(smraw + 32 * HPADH * 2); // 32 x GPAD floats

    const int tid  = threadIdx.x;
    const int warp = tid >> 5, lane = tid & 31;
    const int qr = lane >> 2, qk = lane & 3;
    const int d    = blockIdx.x >> 5;
    const int j0   = (blockIdx.x & 31) * 16;

    // B fragments (fp16): warp covers N-cols 8w..8w+7; fragment n-index = qr
    const int ncol = 8 * warp + qr;
    const int jl_w = ncol >> 2, ty_w = ncol & 3;
    const int grow = ty_w * NC + j0 + jl_w;
    const float* wrow = whh + (size_t)d * G4 * NC + (size_t)grow * NC;
    uint32_t b0r[32], b1r[32];
#pragma unroll
    for (int kt = 0; kt < 32; kt++) {
        const float w0 = __ldg(wrow + kt * 16 + 2 * qk);
        const float w1 = __ldg(wrow + kt * 16 + 2 * qk + 1);
        const float w2 = __ldg(wrow + kt * 16 + 2 * qk + 8);
        const float w3 = __ldg(wrow + kt * 16 + 2 * qk + 9);
        b0r[kt] = h2_as_u32(__floats2half2_rn(w0, w1));
        b1r[kt] = h2_as_u32(__floats2half2_rn(w2, w3));
    }

    const float* xpd = xp + (size_t)d * G4;
    float cst[2] = {0.f, 0.f};
    unsigned gen = 0;

    // activation mapping: (b, j) pairs p = tid and tid+256; prefetch xp for t=0
    float pxi[2], pxf[2], pxg[2], pxo[2];
    {
        const int tt0 = d ? (Tt - 1) : 0;
#pragma unroll
        for (int pp = 0; pp < 2; pp++) {
            const int p2 = tid + pp * 256;
            const int b = p2 >> 4, jl = p2 & 15, j = j0 + jl;
            const float* xpr = xpd + ((size_t)b * Tt + tt0) * G8;
            pxi[pp] = __ldg(xpr + j);
            pxf[pp] = __ldg(xpr + NC + j);
            pxg[pp] = __ldg(xpr + 2 * NC + j);
            pxo[pp] = __ldg(xpr + 3 * NC + j);
        }
    }

    for (int t = 0; t < Tt; t++) {
        const int tt = d ? (Tt - 1 - t) : t;

        if (t > 0) {
            // stage fp16 h_{t-1}: 32 rows x 512 halves = 2048 uint4
            const uint4* src = (const uint4*)g_hbufh[d * 2 + (t & 1)];
#pragma unroll
            for (int r = 0; r < 8; r++) {
                const int idx = r * 256 + tid;
                uint4 v = __ldcg(src + idx);
                const int row = idx >> 6, col = idx & 63;
                *(uint4*)(Hs + row * HPADH + col * 8) = v;
            }
            __syncthreads();

            float acc[2][4];
#pragma unroll
            for (int mt = 0; mt < 2; mt++)
#pragma unroll
                for (int l = 0; l < 4; l++) acc[mt][l] = 0.f;

            const uint32_t* Hs32 = (const uint32_t*)Hs;
#pragma unroll
            for (int kt = 0; kt < 32; kt++) {
                uint32_t b[2] = { b0r[kt], b1r[kt] };
#pragma unroll
                for (int mt = 0; mt < 2; mt++) {
                    const uint32_t* ap = Hs32 + (16 * mt + qr) * (HPADH / 2) + kt * 8 + qk;
                    uint32_t a[4];
                    a[0] = ap[0];
                    a[1] = ap[8 * (HPADH / 2)];
                    a[2] = ap[4];
                    a[3] = ap[8 * (HPADH / 2) + 4];
                    mma_f16(acc[mt], a, b);
                }
            }
#pragma unroll
            for (int mt = 0; mt < 2; mt++) {
                *(float2*)&Gs[(16 * mt + qr) * GPAD + 8 * warp + 2 * qk] =
                    make_float2(acc[mt][0], acc[mt][1]);
                *(float2*)&Gs[(16 * mt + qr + 8) * GPAD + 8 * warp + 2 * qk] =
                    make_float2(acc[mt][2], acc[mt][3]);
            }
            __syncthreads();
        }

#pragma unroll
        for (int pp = 0; pp < 2; pp++) {
            const int p2 = tid + pp * 256;
            const int b = p2 >> 4, jl = p2 & 15, j = j0 + jl;
            float gi = pxi[pp], gf = pxf[pp], gg = pxg[pp], go = pxo[pp];
            if (t > 0) {
                float4 gv = *(const float4*)&Gs[b * GPAD + 4 * jl];
                gi += gv.x; gf += gv.y; gg += gv.z; go += gv.w;
            }
            const float si = fsig(gi);
            const float sf = fsig(gf);
            const float sg = ftanh(gg);
            const float so = fsig(go);
            cst[pp] = sf * cst[pp] + si * sg;
            const float h = so * ftanh(cst[pp]);
            g_hbufh[d * 2 + ((t + 1) & 1)][b * NC + j] = __float2half_rn(h);
            const size_t oidx = ((size_t)b * Tt + tt) * (2 * NC) + d * NC + j;
            if (out)  out[oidx]  = h;
            if (outh) outh[oidx] = __float2half_rn(h);
        }

        // prefetch xp for t+1 (independent of h) before the barrier
        if (t + 1 < Tt) {
            const int ttn = d ? (Tt - 2 - t) : (t + 1);
#pragma unroll
            for (int pp = 0; pp < 2; pp++) {
                const int p2 = tid + pp * 256;
                const int b = p2 >> 4, jl = p2 & 15, j = j0 + jl;
                const float* xpr = xpd + ((size_t)b * Tt + ttn) * G8;
                pxi[pp] = __ldg(xpr + j);
                pxf[pp] = __ldg(xpr + NC + j);
                pxg[pp] = __ldg(xpr + 2 * NC + j);
                pxo[pp] = __ldg(xpr + 3 * NC + j);
            }
            gridbar_dir(d, 32, gen);
        }
    }
}

// ---------------- attention scores ----------------
__global__ __launch_bounds__(256) void scores_kernel(
    const float* __restrict__ h, const float* __restrict__ wu,
    const float* __restrict__ bu, const int* __restrict__ lens,
    float* __restrict__ sc)
{
    const int gid = blockIdx.x * 256 + threadIdx.x;
    const int w = gid >> 5, lane = gid & 31;
    const float* hr = h + (size_t)w * (2 * NC);
    float s = 0.f;
    for (int i = lane; i < 2 * NC; i += 32) s = fmaf(hr[i], wu[i], s);
#pragma unroll
    for (int o = 16; o; o >>= 1) s += __shfl_xor_sync(0xffffffffu, s, o);
    if (lane == 0) {
        const int b = w >> 9, t = w & 511;
        sc[w] = (t < lens[b]) ? (s + bu[0]) : -INFINITY;
    }
}

// ---------------- masked softmax + weighted pool ----------------
__global__ __launch_bounds__(256) void softpool_kernel(
    const float* __restrict__ h, const float* __restrict__ sc,
    float* __restrict__ pooled)
{
    const int b = blockIdx.x, tid = threadIdx.x;
    __shared__ float al[512];
    __shared__ float red[256];
    float m = -INFINITY;
    for (int t = tid; t < 512; t += 256) m = fmaxf(m, sc[b * 512 + t]);
    red[tid] = m; __syncthreads();
    for (int o = 128; o; o >>= 1) {
        if (tid < o) red[tid] = fmaxf(red[tid], red[tid + o]);
        __syncthreads();
    }
    m = red[0]; __syncthreads();
    float s = 0.f;
    for (int t = tid; t < 512; t += 256) {
        const float e = expf(sc[b * 512 + t] - m);
        al[t] = e; s += e;
    }
    red[tid] = s; __syncthreads();
    for (int o = 128; o; o >>= 1) {
        if (tid < o) red[tid] += red[tid + o];
        __syncthreads();
    }
    const float inv = 1.f / red[0];
    __syncthreads();
    for (int d2 = tid; d2 < 2 * NC; d2 += 256) {
        float acc = 0.f;
        for (int t = 0; t < 512; t++)
            acc = fmaf(al[t], h[((size_t)b * 512 + t) * (2 * NC) + d2], acc);
        pooled[b * (2 * NC) + d2] = acc * inv;
    }
}

// ---------------- final classifier ----------------
__global__ __launch_bounds__(256) void final_kernel(
    const float* __restrict__ pooled, const float* __restrict__ Wc,
    const float* __restrict__ bc, float* __restrict__ out)
{
    const int tid = threadIdx.x;
    const int b = tid >> 3, o = tid & 7;
    const float* p = pooled + b * (2 * NC);
    const float* w = Wc + o * (2 * NC);
    float acc = bc[o];
    for (int k = 0; k < 2 * NC; k++) acc = fmaf(p[k], w[k], acc);
    out[b * NOUT + o] = acc;
}

// ---------------- launch ----------------
extern "C" void kernel_launch(void* const* d_in, const int* in_sizes, int n_in,
                              void* d_out, int out_size)
{
    const float* x    = (const float*)d_in[0];
    const int*   lens = (const int*)  d_in[1];
    const float* W1   = (const float*)d_in[2];
    const float* b1   = (const float*)d_in[3];
    const float* g1   = (const float*)d_in[4];
    const float* be1  = (const float*)d_in[5];
    const float* W2   = (const float*)d_in[6];
    const float* b2   = (const float*)d_in[7];
    const float* g2   = (const float*)d_in[8];
    const float* be2  = (const float*)d_in[9];
    const float* wih  = (const float*)d_in[10];
    const float* whh  = (const float*)d_in[11];
    const float* bih  = (const float*)d_in[12];
    const float* bhh  = (const float*)d_in[13];
    const float* wu   = (const float*)d_in[14];
    const float* bu   = (const float*)d_in[15];
    const float* Wc   = (const float*)d_in[16];
    const float* bc   = (const float*)d_in[17];
    float* out = (float*)d_out;

    float  *h1, *h2, *xpb, *l1, *sc, *pooled;
    __half *xh, *h1h, *h2h, *l0h, *w1h, *w2h, *wihh;
    cudaGetSymbolAddress((void**)&h1, g_h1);
    cudaGetSymbolAddress((void**)&h2, g_h2);
    cudaGetSymbolAddress((void**)&xpb, g_xp);
    cudaGetSymbolAddress((void**)&l1, g_l1);
    cudaGetSymbolAddress((void**)&sc, g_sc);
    cudaGetSymbolAddress((void**)&pooled, g_pooled);
    cudaGetSymbolAddress((void**)&xh, g_xh);
    cudaGetSymbolAddress((void**)&h1h, g_h1h);
    cudaGetSymbolAddress((void**)&h2h, g_h2h);
    cudaGetSymbolAddress((void**)&l0h, g_l0h);
    cudaGetSymbolAddress((void**)&w1h, g_w1h);
    cudaGetSymbolAddress((void**)&w2h, g_w2h);
    cudaGetSymbolAddress((void**)&wihh, g_wihh);

    const int lstm_smem = 32 * HPADH * 2 + 32 * GPAD * 4;
    cudaFuncSetAttribute(lstm_tc_kernel,
                         cudaFuncAttributeMaxDynamicSharedMemorySize, lstm_smem);

    // one-shot fp32 -> fp16 operand conversion
    cvt_f16_kernel<<<(MT * FDim / 4 + 255) / 256, 256>>>((const float4*)x, (uint2*)xh, MT * FDim / 4);
    cvt_f16_kernel<<<(NH * FDim / 4 + 255) / 256, 256>>>((const float4*)W1, (uint2*)w1h, NH * FDim / 4);
    cvt_f16_kernel<<<(NH * NH / 4 + 255) / 256, 256>>>((const float4*)W2, (uint2*)w2h, NH * NH / 4);
    cvt_f16_kernel<<<(2 * G8 * NH / 4 + 255) / 256, 256>>>((const float4*)wih, (uint2*)wihh, 2 * G8 * NH / 4);

    // MLP
    gemm_f16_kernel<<<dim3(NH / 128, MT / 128), 256>>>(xh, w1h, b1, nullptr, h1, MT, NH, FDim);
    ln_lrelu_kernel<<<MT, 256>>>(h1, h1h, g1, be1, nullptr, 0);
    gemm_f16_kernel<<<dim3(NH / 128, MT / 128), 256>>>(h1h, w2h, b2, nullptr, h2, MT, NH, NH);
    ln_lrelu_kernel<<<MT, 256>>>(h2, h2h, g2, be2, lens, 1);

    // LSTM layer 0: fp16 out only (feeds layer-1 GEMM)
    gemm_f16_kernel<<<dim3(G8 / 128, MT / 128), 256>>>(
        h2h, wihh, bih, bhh, xpb, MT, G8, NH);
    reset_bar_kernel<<<1, 32>>>();
    lstm_tc_kernel<<<64, 256, lstm_smem>>>(xpb, whh, nullptr, l0h);

    // LSTM layer 1: fp32 out only (feeds attention)
    gemm_f16_kernel<<<dim3(G8 / 128, MT / 128), 256>>>(
        l0h, wihh + (size_t)G8 * NH,
        bih + G8, bhh + G8, xpb, MT, G8, NH);
    reset_bar_kernel<<<1, 32>>>();
    lstm_tc_kernel<<<64, 256, lstm_smem>>>(xpb, whh + (size_t)2 * G4 * NC, l1, nullptr);

    // attention + head
    scores_kernel<<<MT / 8, 256>>>(l1, wu, bu, lens, sc);
    softpool_kernel<<<Bq, 256>>>(l1, sc, pooled);
    final_kernel<<<1, 256>>>(pooled, Wc, bc, out);
}

// round 16
// speedup vs baseline: 1.5921x; 1.0760x over previous
#include <cuda_runtime.h>
#include <cuda_fp16.h>
#include <math.h>
#include <stdint.h>
#include <string.h>

#define Bq   32
#define Tt   512
#define FDim 256
#define NH   1024
#define NC   512
#define G4   2048      // 4*NC
#define G8   4096      // 2 dirs * 4*NC
#define NOUT 8
#define MT   (Bq*Tt)   // 16384 rows

// ---------------- device scratch ----------------
__device__ float  g_h1[(size_t)MT*NH];
__device__ float  g_h2[(size_t)MT*NH];
__device__ float  g_xp[(size_t)MT*G8];         // [(b*T+t)][dir*G4 + g]
__device__ float  g_l1[(size_t)MT*2*NC];
__device__ __half g_hbufh[4][Bq*NC];           // [dir*2+parity][b][j], fp16 h state
__device__ float  g_sc[Bq*Tt];
__device__ float  g_pooled[Bq*2*NC];
__device__ __half g_xh[(size_t)MT*FDim];
__device__ __half g_h1h[(size_t)MT*NH];
__device__ __half g_h2h[(size_t)MT*NH];
__device__ __half g_l0h[(size_t)MT*2*NC];
__device__ __half g_w1h[(size_t)NH*FDim];
__device__ __half g_w2h[(size_t)NH*NH];
__device__ __half g_wihh[(size_t)2*G8*NH];
// per-direction barrier state, separate cache lines
__device__ unsigned g_bar_arrive2[2][32];
__device__ unsigned g_bar_gen2[2][32];

// ---------------- per-direction grid barrier (single counter + single gen word) ----------------
__device__ __forceinline__ void gridbar_dir(int d, unsigned nb, unsigned &gen) {
    __syncthreads();
    if (threadIdx.x == 0) {
        gen++;
        unsigned prev;
        asm volatile("atom.add.release.gpu.u32 %0, [%1], 1;"
                     : "=r"(prev) : "l"(&g_bar_arrive2[d][0]) : "memory");
        if (prev == nb * gen - 1u) {
            asm volatile("st.release.gpu.u32 [%0], %1;"
                         :: "l"(&g_bar_gen2[d][0]), "r"(gen) : "memory");
        } else {
            unsigned cur;
            do {
                asm volatile("ld.acquire.gpu.u32 %0, [%1];"
                             : "=r"(cur) : "l"(&g_bar_gen2[d][0]) : "memory");
            } while (cur < gen);
        }
    }
    __syncthreads();
}

__global__ void reset_bar_kernel() {
    if (threadIdx.x < 2) {
        g_bar_arrive2[threadIdx.x][0] = 0u;
        g_bar_gen2[threadIdx.x][0] = 0u;
    }
}

// ---------------- helpers ----------------
__device__ __forceinline__ unsigned su32(const void* p) {
    unsigned r;
    asm("{.reg .u64 t; cvta.to.shared.u64 t, %1; cvt.u32.u64 %0, t;}" : "=r"(r) : "l"(p));
    return r;
}
__device__ __forceinline__ void cp16(unsigned s, const void* g) {
    asm volatile("cp.async.cg.shared.global [%0], [%1], 16;\n" :: "r"(s), "l"(g));
}
__device__ __forceinline__ uint32_t h2_as_u32(__half2 h) {
    __half2_raw r = *(__half2_raw*)&h;
    return (uint32_t)r.x | ((uint32_t)r.y << 16);
}
__device__ __forceinline__ float fexp(float x) {
    float r;
    asm("ex2.approx.f32 %0, %1;" : "=f"(r) : "f"(x * 1.4426950408889634f));
    return r;
}
__device__ __forceinline__ float fsig(float x) {
    return __fdividef(1.f, 1.f + fexp(-x));
}
__device__ __forceinline__ float ftanh(float x) {
    const float xx = fminf(fmaxf(x, -15.f), 15.f);
    const float e = fexp(2.f * xx);
    return __fdividef(e - 1.f, e + 1.f);
}
__device__ __forceinline__ void mma_f16(float (&c)[4], const uint32_t (&a)[4], const uint32_t (&b)[2]) {
    asm volatile("mma.sync.aligned.m16n8k16.row.col.f32.f16.f16.f32 "
        "{%0,%1,%2,%3}, {%4,%5,%6,%7}, {%8,%9}, {%0,%1,%2,%3};\n"
        : "+f"(c[0]), "+f"(c[1]), "+f"(c[2]), "+f"(c[3])
        : "r"(a[0]), "r"(a[1]), "r"(a[2]), "r"(a[3]), "r"(b[0]), "r"(b[1]));
}

// ---------------- elementwise fp32 -> fp16 ----------------
__global__ __launch_bounds__(256) void cvt_f16_kernel(
    const float4* __restrict__ src, uint2* __restrict__ dst, int n4)
{
    const int i = blockIdx.x * 256 + threadIdx.x;
    if (i < n4) {
        float4 v = src[i];
        uint2 o;
        o.x = h2_as_u32(__floats2half2_rn(v.x, v.y));
        o.y = h2_as_u32(__floats2half2_rn(v.z, v.w));
        dst[i] = o;
    }
}

// ---------------- fp16 GEMM: C = A[M,K]*W[N,K]^T + b1 (+b2), fp32 accum/out ----------------
#define PADH 40
__global__ __launch_bounds__(256) void gemm_f16_kernel(
    const __half* __restrict__ A, const __half* __restrict__ W,
    const float* __restrict__ bias1, const float* __restrict__ bias2,
    float* __restrict__ C, int M, int N, int K)
{
    __shared__ __half As[2][128 * PADH];
    __shared__ __half Ws[2][128 * PADH];
    const int tid  = threadIdx.x;
    const int warp = tid >> 5, lane = tid & 31;
    const int wm = warp & 3, wn = warp >> 2;
    const int qr = lane >> 2, qk = lane & 3;
    const int m0 = blockIdx.y * 128;
    const int n0 = blockIdx.x * 128;

    const int ca = tid * 2, cb = ca + 1;
    const int ra = ca >> 2, ka = (ca & 3) * 8;
    const int rb = cb >> 2, kb = (cb & 3) * 8;

    const __half* Ag = A + (size_t)m0 * K;
    const __half* Wg = W + (size_t)n0 * K;

    const unsigned sAa = su32(&As[0][ra * PADH + ka]);
    const unsigned sAb = su32(&As[0][rb * PADH + kb]);
    const unsigned sWa = su32(&Ws[0][ra * PADH + ka]);
    const unsigned sWb = su32(&Ws[0][rb * PADH + kb]);
    const unsigned stgB = 128 * PADH * 2;

    float acc[2][8][4];
#pragma unroll
    for (int i = 0; i < 2; i++)
#pragma unroll
        for (int j = 0; j < 8; j++)
#pragma unroll
            for (int l = 0; l < 4; l++) acc[i][j][l] = 0.f;

    const int nk = K >> 5;

    cp16(sAa, Ag + (size_t)ra * K + ka);
    cp16(sAb, Ag + (size_t)rb * K + kb);
    cp16(sWa, Wg + (size_t)ra * K + ka);
    cp16(sWb, Wg + (size_t)rb * K + kb);
    asm volatile("cp.async.commit_group;\n");

    for (int kt = 0; kt < nk; kt++) {
        if (kt + 1 < nk) {
            const int k0 = (kt + 1) * 32;
            const unsigned so = ((kt + 1) & 1) * stgB;
            cp16(sAa + so, Ag + (size_t)ra * K + k0 + ka);
            cp16(sAb + so, Ag + (size_t)rb * K + k0 + kb);
            cp16(sWa + so, Wg + (size_t)ra * K + k0 + ka);
            cp16(sWb + so, Wg + (size_t)rb * K + k0 + kb);
            asm volatile("cp.async.commit_group;\n");
            asm volatile("cp.async.wait_group 1;\n");
        } else {
            asm volatile("cp.async.wait_group 0;\n");
        }
        __syncthreads();

        const uint32_t* Ab_ = (const uint32_t*)&As[kt & 1][0];
        const uint32_t* Bb_ = (const uint32_t*)&Ws[kt & 1][0];
#pragma unroll
        for (int ks = 0; ks < 32; ks += 16) {
            uint32_t a[2][4];
#pragma unroll
            for (int mt = 0; mt < 2; mt++) {
                const uint32_t* ap = Ab_ + (wm * 32 + mt * 16 + qr) * (PADH / 2) + (ks >> 1) + qk;
                a[mt][0] = ap[0];
                a[mt][1] = ap[8 * (PADH / 2)];
                a[mt][2] = ap[4];
                a[mt][3] = ap[8 * (PADH / 2) + 4];
            }
#pragma unroll
            for (int nt = 0; nt < 8; nt++) {
                const uint32_t* bp = Bb_ + (wn * 64 + nt * 8 + qr) * (PADH / 2) + (ks >> 1) + qk;
                uint32_t b[2];
                b[0] = bp[0];
                b[1] = bp[4];
                mma_f16(acc[0][nt], a[0], b);
                mma_f16(acc[1][nt], a[1], b);
            }
        }
        __syncthreads();
    }

#pragma unroll
    for (int mt = 0; mt < 2; mt++) {
        const int mr = m0 + wm * 32 + mt * 16 + qr;
#pragma unroll
        for (int nt = 0; nt < 8; nt++) {
            const int n = n0 + wn * 64 + nt * 8 + qk * 2;
            float b0 = bias1[n], b1 = bias1[n + 1];
            if (bias2) { b0 += bias2[n]; b1 += bias2[n + 1]; }
            *(float2*)&C[(size_t)mr * N + n]       = make_float2(acc[mt][nt][0] + b0, acc[mt][nt][1] + b1);
            *(float2*)&C[(size_t)(mr + 8) * N + n] = make_float2(acc[mt][nt][2] + b0, acc[mt][nt][3] + b1);
        }
    }
}

// ---------------- LayerNorm + LeakyReLU (+ mask): fp32 in, fp16 out ----------------
__global__ __launch_bounds__(256) void ln_lrelu_kernel(
    const float* __restrict__ X, __half* __restrict__ Xh,
    const float* __restrict__ gm, const float* __restrict__ bt,
    const int* __restrict__ lens, int domask)
{
    const int row = blockIdx.x;
    const int tid = threadIdx.x;
    const float4* Xr = (const float4*)(X + (size_t)row * NH);
    float4 v = Xr[tid];
    __shared__ float rs[256], rq[256];
    rs[tid] = v.x + v.y + v.z + v.w;
    rq[tid] = v.x * v.x + v.y * v.y + v.z * v.z + v.w * v.w;
    __syncthreads();
    for (int o = 128; o; o >>= 1) {
        if (tid < o) { rs[tid] += rs[tid + o]; rq[tid] += rq[tid + o]; }
        __syncthreads();
    }
    const float mean = rs[0] * (1.f / NH);
    const float var  = rq[0] * (1.f / NH) - mean * mean;
    const float rstd = rsqrtf(var + 1e-5f);
    float mul = 1.f;
    if (domask) {
        const int b = row >> 9, t = row & 511;
        if (t >= lens[b]) mul = 0.f;
    }
    const int gb = tid * 4;
    float y0 = (v.x - mean) * rstd * gm[gb + 0] + bt[gb + 0];
    float y1 = (v.y - mean) * rstd * gm[gb + 1] + bt[gb + 1];
    float y2 = (v.z - mean) * rstd * gm[gb + 2] + bt[gb + 2];
    float y3 = (v.w - mean) * rstd * gm[gb + 3] + bt[gb + 3];
    y0 = (y0 >= 0.f ? y0 : 0.01f * y0) * mul;
    y1 = (y1 >= 0.f ? y1 : 0.01f * y1) * mul;
    y2 = (y2 >= 0.f ? y2 : 0.01f * y2) * mul;
    y3 = (y3 >= 0.f ? y3 : 0.01f * y3) * mul;
    uint2 o;
    o.x = h2_as_u32(__floats2half2_rn(y0, y1));
    o.y = h2_as_u32(__floats2half2_rn(y2, y3));
    ((uint2*)(Xh + (size_t)row * NH))[tid] = o;
}

// ---------------- persistent fp16 tensor-core bidirectional LSTM layer ----------------
// 128 blocks x 256 threads. d = bid>>6; block owns 8 hidden units (32 N-cols).
// Warps: kh = warp>>2 (K half), wn = warp&3 (ncols 8wn..8wn+7).
// Per-direction single-counter barrier (64 arrivals). Activation: 1 (b,j)/thread.
#define HPADH 520
#define GPADL 36
__global__ __launch_bounds__(256, 1) void lstm_tc_kernel(
    const float* __restrict__ xp,    // [MT][G8], dir at col offset d*G4
    const float* __restrict__ whh,   // [2][G4][NC] for this layer
    float* __restrict__ out,         // optional fp32 out [(b*T+t)][2*NC]
    __half* __restrict__ outh)       // optional fp16 out
{
    extern __shared__ char smraw[];
    __half* Hs = (__half*)smraw;                    // 32 x HPADH halves
    float*  Gs = (float*)(smraw + 32 * HPADH * 2);  // 2 x 32 x GPADL floats

    const int tid  = threadIdx.x;
    const int warp = tid >> 5, lane = tid & 31;
    const int qr = lane >> 2, qk = lane & 3;
    const int d   = blockIdx.x >> 6;
    const int j0  = (blockIdx.x & 63) * 8;
    const int kh  = warp >> 2, wn = warp & 3;

    // B fragments (fp16): ncol = 8*wn + qr; K-half kh
    const int ncol = 8 * wn + qr;
    const int jl_w = ncol >> 2, ty_w = ncol & 3;
    const int grow = ty_w * NC + j0 + jl_w;
    const float* wrow = whh + (size_t)d * G4 * NC + (size_t)grow * NC + kh * 256;
    uint32_t b0r[16], b1r[16];
#pragma unroll
    for (int kt = 0; kt < 16; kt++) {
        const float w0 = __ldg(wrow + kt * 16 + 2 * qk);
        const float w1 = __ldg(wrow + kt * 16 + 2 * qk + 1);
        const float w2 = __ldg(wrow + kt * 16 + 2 * qk + 8);
        const float w3 = __ldg(wrow + kt * 16 + 2 * qk + 9);
        b0r[kt] = h2_as_u32(__floats2half2_rn(w0, w1));
        b1r[kt] = h2_as_u32(__floats2half2_rn(w2, w3));
    }

    // activation mapping: one (b, j) per thread
    const int ab = tid >> 3, ajl = tid & 7, aj = j0 + ajl;
    const float* xpd = xp + (size_t)d * G4;
    float cst = 0.f;
    unsigned gen = 0;

    // prefetch xp for t = 0
    const int tt0 = d ? (Tt - 1) : 0;
    const float* xpr0 = xpd + ((size_t)ab * Tt + tt0) * G8;
    float pxi = __ldg(xpr0 + aj);
    float pxf = __ldg(xpr0 + NC + aj);
    float pxg = __ldg(xpr0 + 2 * NC + aj);
    float pxo = __ldg(xpr0 + 3 * NC + aj);

    for (int t = 0; t < Tt; t++) {
        const int tt = d ? (Tt - 1 - t) : t;

        if (t > 0) {
            // stage fp16 h_{t-1}: 32 rows x 512 halves = 2048 uint4
            const uint4* src = (const uint4*)g_hbufh[d * 2 + (t & 1)];
#pragma unroll
            for (int r = 0; r < 8; r++) {
                const int idx = r * 256 + tid;
                uint4 v = __ldcg(src + idx);
                const int row = idx >> 6, col = idx & 63;
                *(uint4*)(Hs + row * HPADH + col * 8) = v;
            }
            __syncthreads();

            float acc[2][4];
#pragma unroll
            for (int mt = 0; mt < 2; mt++)
#pragma unroll
                for (int l = 0; l < 4; l++) acc[mt][l] = 0.f;

            const uint32_t* Hs32 = (const uint32_t*)Hs;
            const int kb_ = kh * 16;
#pragma unroll
            for (int kt = 0; kt < 16; kt++) {
                uint32_t b[2] = { b0r[kt], b1r[kt] };
#pragma unroll
                for (int mt = 0; mt < 2; mt++) {
                    const uint32_t* ap = Hs32 + (16 * mt + qr) * (HPADH / 2) + (kb_ + kt) * 8 + qk;
                    uint32_t a[4];
                    a[0] = ap[0];
                    a[1] = ap[8 * (HPADH / 2)];
                    a[2] = ap[4];
                    a[3] = ap[8 * (HPADH / 2) + 4];
                    mma_f16(acc[mt], a, b);
                }
            }
            float* Gk = Gs + kh * 32 * GPADL;
#pragma unroll
            for (int mt = 0; mt < 2; mt++) {
                *(float2*)&Gk[(16 * mt + qr) * GPADL + 8 * wn + 2 * qk] =
                    make_float2(acc[mt][0], acc[mt][1]);
                *(float2*)&Gk[(16 * mt + qr + 8) * GPADL + 8 * wn + 2 * qk] =
                    make_float2(acc[mt][2], acc[mt][3]);
            }
            __syncthreads();
        }

        // ---- activation: single (b, j) per thread ----
        {
            float gi = pxi, gf = pxf, gg = pxg, go = pxo;
            if (t > 0) {
                float4 g0 = *(const float4*)&Gs[ab * GPADL + 4 * ajl];
                float4 g1 = *(const float4*)&Gs[32 * GPADL + ab * GPADL + 4 * ajl];
                gi += g0.x + g1.x; gf += g0.y + g1.y;
                gg += g0.z + g1.z; go += g0.w + g1.w;
            }
            const float si = fsig(gi);
            const float sf = fsig(gf);
            const float sg = ftanh(gg);
            const float so = fsig(go);
            cst = sf * cst + si * sg;
            const float h = so * ftanh(cst);
            __stcg((__half*)&g_hbufh[d * 2 + ((t + 1) & 1)][ab * NC + aj], __float2half_rn(h));
            const size_t oidx = ((size_t)ab * Tt + tt) * (2 * NC) + d * NC + aj;
            if (out)  out[oidx]  = h;
            if (outh) outh[oidx] = __float2half_rn(h);
        }

        // prefetch xp for t+1 (independent of h) before the barrier
        if (t + 1 < Tt) {
            const int ttn = d ? (Tt - 2 - t) : (t + 1);
            const float* xpr = xpd + ((size_t)ab * Tt + ttn) * G8;
            pxi = __ldg(xpr + aj);
            pxf = __ldg(xpr + NC + aj);
            pxg = __ldg(xpr + 2 * NC + aj);
            pxo = __ldg(xpr + 3 * NC + aj);
            gridbar_dir(d, 64, gen);
        }
    }
}

// ---------------- attention scores ----------------
__global__ __launch_bounds__(256) void scores_kernel(
    const float* __restrict__ h, const float* __restrict__ wu,
    const float* __restrict__ bu, const int* __restrict__ lens,
    float* __restrict__ sc)
{
    const int gid = blockIdx.x * 256 + threadIdx.x;
    const int w = gid >> 5, lane = gid & 31;
    const float* hr = h + (size_t)w * (2 * NC);
    float s = 0.f;
    for (int i = lane; i < 2 * NC; i += 32) s = fmaf(hr[i], wu[i], s);
#pragma unroll
    for (int o = 16; o; o >>= 1) s += __shfl_xor_sync(0xffffffffu, s, o);
    if (lane == 0) {
        const int b = w >> 9, t = w & 511;
        sc[w] = (t < lens[b]) ? (s + bu[0]) : -INFINITY;
    }
}

// ---------------- masked softmax + weighted pool ----------------
__global__ __launch_bounds__(256) void softpool_kernel(
    const float* __restrict__ h, const float* __restrict__ sc,
    float* __restrict__ pooled)
{
    const int b = blockIdx.x, tid = threadIdx.x;
    __shared__ float al[512];
    __shared__ float red[256];
    float m = -INFINITY;
    for (int t = tid; t < 512; t += 256) m = fmaxf(m, sc[b * 512 + t]);
    red[tid] = m; __syncthreads();
    for (int o = 128; o; o >>= 1) {
        if (tid < o) red[tid] = fmaxf(red[tid], red[tid + o]);
        __syncthreads();
    }
    m = red[0]; __syncthreads();
    float s = 0.f;
    for (int t = tid; t < 512; t += 256) {
        const float e = expf(sc[b * 512 + t] - m);
        al[t] = e; s += e;
    }
    red[tid] = s; __syncthreads();
    for (int o = 128; o; o >>= 1) {
        if (tid < o) red[tid] += red[tid + o];
        __syncthreads();
    }
    const float inv = 1.f / red[0];
    __syncthreads();
    for (int d2 = tid; d2 < 2 * NC; d2 += 256) {
        float acc = 0.f;
        for (int t = 0; t < 512; t++)
            acc = fmaf(al[t], h[((size_t)b * 512 + t) * (2 * NC) + d2], acc);
        pooled[b * (2 * NC) + d2] = acc * inv;
    }
}

// ---------------- final classifier ----------------
__global__ __launch_bounds__(256) void final_kernel(
    const float* __restrict__ pooled, const float* __restrict__ Wc,
    const float* __restrict__ bc, float* __restrict__ out)
{
    const int tid = threadIdx.x;
    const int b = tid >> 3, o = tid & 7;
    const float* p = pooled + b * (2 * NC);
    const float* w = Wc + o * (2 * NC);
    float acc = bc[o];
    for (int k = 0; k < 2 * NC; k++) acc = fmaf(p[k], w[k], acc);
    out[b * NOUT + o] = acc;
}

// ---------------- launch ----------------
extern "C" void kernel_launch(void* const* d_in, const int* in_sizes, int n_in,
                              void* d_out, int out_size)
{
    const float* x    = (const float*)d_in[0];
    const int*   lens = (const int*)  d_in[1];
    const float* W1   = (const float*)d_in[2];
    const float* b1   = (const float*)d_in[3];
    const float* g1   = (const float*)d_in[4];
    const float* be1  = (const float*)d_in[5];
    const float* W2   = (const float*)d_in[6];
    const float* b2   = (const float*)d_in[7];
    const float* g2   = (const float*)d_in[8];
    const float* be2  = (const float*)d_in[9];
    const float* wih  = (const float*)d_in[10];
    const float* whh  = (const float*)d_in[11];
    const float* bih  = (const float*)d_in[12];
    const float* bhh  = (const float*)d_in[13];
    const float* wu   = (const float*)d_in[14];
    const float* bu   = (const float*)d_in[15];
    const float* Wc   = (const float*)d_in[16];
    const float* bc   = (const float*)d_in[17];
    float* out = (float*)d_out;

    float  *h1, *h2, *xpb, *l1, *sc, *pooled;
    __half *xh, *h1h, *h2h, *l0h, *w1h, *w2h, *wihh;
    cudaGetSymbolAddress((void**)&h1, g_h1);
    cudaGetSymbolAddress((void**)&h2, g_h2);
    cudaGetSymbolAddress((void**)&xpb, g_xp);
    cudaGetSymbolAddress((void**)&l1, g_l1);
    cudaGetSymbolAddress((void**)&sc, g_sc);
    cudaGetSymbolAddress((void**)&pooled, g_pooled);
    cudaGetSymbolAddress((void**)&xh, g_xh);
    cudaGetSymbolAddress((void**)&h1h, g_h1h);
    cudaGetSymbolAddress((void**)&h2h, g_h2h);
    cudaGetSymbolAddress((void**)&l0h, g_l0h);
    cudaGetSymbolAddress((void**)&w1h, g_w1h);
    cudaGetSymbolAddress((void**)&w2h, g_w2h);
    cudaGetSymbolAddress((void**)&wihh, g_wihh);

    const int lstm_smem = 32 * HPADH * 2 + 2 * 32 * GPADL * 4;
    cudaFuncSetAttribute(lstm_tc_kernel,
                         cudaFuncAttributeMaxDynamicSharedMemorySize, lstm_smem);

    // one-shot fp32 -> fp16 operand conversion
    cvt_f16_kernel<<<(MT * FDim / 4 + 255) / 256, 256>>>((const float4*)x, (uint2*)xh, MT * FDim / 4);
    cvt_f16_kernel<<<(NH * FDim / 4 + 255) / 256, 256>>>((const float4*)W1, (uint2*)w1h, NH * FDim / 4);
    cvt_f16_kernel<<<(NH * NH / 4 + 255) / 256, 256>>>((const float4*)W2, (uint2*)w2h, NH * NH / 4);
    cvt_f16_kernel<<<(2 * G8 * NH / 4 + 255) / 256, 256>>>((const float4*)wih, (uint2*)wihh, 2 * G8 * NH / 4);

    // MLP
    gemm_f16_kernel<<<dim3(NH / 128, MT / 128), 256>>>(xh, w1h, b1, nullptr, h1, MT, NH, FDim);
    ln_lrelu_kernel<<<MT, 256>>>(h1, h1h, g1, be1, nullptr, 0);
    gemm_f16_kernel<<<dim3(NH / 128, MT / 128), 256>>>(h1h, w2h, b2, nullptr, h2, MT, NH, NH);
    ln_lrelu_kernel<<<MT, 256>>>(h2, h2h, g2, be2, lens, 1);

    // LSTM layer 0: fp16 out only (feeds layer-1 GEMM)
    gemm_f16_kernel<<<dim3(G8 / 128, MT / 128), 256>>>(
        h2h, wihh, bih, bhh, xpb, MT, G8, NH);
    reset_bar_kernel<<<1, 32>>>();
    lstm_tc_kernel<<<128, 256, lstm_smem>>>(xpb, whh, nullptr, l0h);

    // LSTM layer 1: fp32 out only (feeds attention)
    gemm_f16_kernel<<<dim3(G8 / 128, MT / 128), 256>>>(
        l0h, wihh + (size_t)G8 * NH,
        bih + G8, bhh + G8, xpb, MT, G8, NH);
    reset_bar_kernel<<<1, 32>>>();
    lstm_tc_kernel<<<128, 256, lstm_smem>>>(xpb, whh + (size_t)2 * G4 * NC, l1, nullptr);

    // attention + head
    scores_kernel<<<MT / 8, 256>>>(l1, wu, bu, lens, sc);
    softpool_kernel<<<Bq, 256>>>(l1, sc, pooled);
    final_kernel<<<1, 256>>>(pooled, Wc, bc, out);
}